// round 14
// baseline (speedup 1.0000x reference)
#include <cuda_runtime.h>
#include <cuda_bf16.h>
#include <cstdint>

#define BB 2
#define NN 2048
#define DIN 512
#define HH 8
#define FF 64
#define HF 512
#define TILES 16
#define NSPL 2
#define LOG2E 1.4426950408889634f

__device__ __nv_bfloat16 g_nodes_bf[(size_t)BB*NN*DIN];
__device__ __nv_bfloat16 g_w_bf[DIN*HF];
__device__ float g_mapped[(size_t)BB*NN*HF];
__device__ float g_el[BB*NN*HH];
__device__ float g_er[BB*NN*HH];
__device__ float g_pacc[(size_t)NSPL*BB*NN*HH*FF];   // 33.6 MB partial acc
__device__ float g_pl[NSPL*BB*NN*HH];                // partial row sums
__device__ __align__(16) unsigned char g_eb[(size_t)BB*NN*NN];

__device__ __forceinline__ uint32_t smem_u32(const void* p){
    uint32_t a; asm("{ .reg .u64 t; cvta.to.shared.u64 t, %1; cvt.u32.u64 %0, t; }" : "=r"(a) : "l"(p)); return a;
}

#define MMA(c, a, b0, b1) asm volatile( \
    "mma.sync.aligned.m16n8k16.row.col.f32.bf16.bf16.f32 " \
    "{%0,%1,%2,%3}, {%4,%5,%6,%7}, {%8,%9}, {%0,%1,%2,%3};" \
    : "+f"((c)[0]), "+f"((c)[1]), "+f"((c)[2]), "+f"((c)[3]) \
    : "r"((a)[0]), "r"((a)[1]), "r"((a)[2]), "r"((a)[3]), "r"(b0), "r"(b1))

#define LDSM4(r, addr) asm volatile( \
    "ldmatrix.sync.aligned.m8n8.x4.shared.b16 {%0,%1,%2,%3}, [%4];" \
    : "=r"((r)[0]), "=r"((r)[1]), "=r"((r)[2]), "=r"((r)[3]) : "r"(addr))

#define LDSM4T(r, addr) asm volatile( \
    "ldmatrix.sync.aligned.m8n8.x4.trans.shared.b16 {%0,%1,%2,%3}, [%4];" \
    : "=r"((r)[0]), "=r"((r)[1]), "=r"((r)[2]), "=r"((r)[3]) : "r"(addr))

// ---------------- f32 -> bf16 input packs --------------------------------------
__global__ __launch_bounds__(256) void cvt_nodes_kernel(const float4* __restrict__ src) {
    int i = blockIdx.x * 256 + threadIdx.x;
    float4 v = src[i];
    uint2 o;
    asm("cvt.rn.bf16x2.f32 %0, %1, %2;" : "=r"(o.x) : "f"(v.y), "f"(v.x));
    asm("cvt.rn.bf16x2.f32 %0, %1, %2;" : "=r"(o.y) : "f"(v.w), "f"(v.z));
    ((uint2*)g_nodes_bf)[i] = o;
}
__global__ __launch_bounds__(256) void cvt_w_kernel(const float4* __restrict__ src) {
    int i = blockIdx.x * 256 + threadIdx.x;
    float4 v = src[i];
    uint2 o;
    asm("cvt.rn.bf16x2.f32 %0, %1, %2;" : "=r"(o.x) : "f"(v.y), "f"(v.x));
    asm("cvt.rn.bf16x2.f32 %0, %1, %2;" : "=r"(o.y) : "f"(v.w), "f"(v.z));
    ((uint2*)g_w_bf)[i] = o;
}

// ---------------- GEMM: mapped = nodes @ W via HMMA bf16 (f32 out) ------------
__global__ __launch_bounds__(256) void gemm_hmma_kernel(void) {
    __shared__ __align__(16) char smA[16384];
    __shared__ __align__(16) char smB[8192];
    const uint32_t sa = smem_u32(smA), sbm = smem_u32(smB);
    const int tid = threadIdx.x, w = tid >> 5, lane = tid & 31;
    const int bn = blockIdx.x * 64, bm = blockIdx.y * 128;
    const int mbase = (w & 3) * 32, nbase = (w >> 2) * 32;
    const int g = lane >> 2, t = lane & 3;

    float c[2][4][4];
#pragma unroll
    for (int mi = 0; mi < 2; mi++)
#pragma unroll
        for (int ng = 0; ng < 4; ng++)
#pragma unroll
            for (int r = 0; r < 4; r++) c[mi][ng][r] = 0.f;

    const int arow0 = lane & 15, akh = lane >> 4;
    const int joff = ((lane >> 3) & 1) * 8 + (lane & 7);
    const int fmb  = (lane >> 4) * 8;
    const uint32_t swb = (uint32_t)((lane & 7) << 4);

    for (int kc = 0; kc < 8; kc++) {
        const int k0 = kc * 64;
        __syncthreads();
        {
            const int row = tid >> 1, half = tid & 1;
            const uint4* src = (const uint4*)(g_nodes_bf + (size_t)(bm + row) * DIN + k0 + half * 32);
            uint4 v0 = src[0], v1 = src[1], v2 = src[2], v3 = src[3];
            const uint32_t sw = (uint32_t)((row & 7) << 4);
            char* rbase = smA + row * 128;
            *(uint4*)(rbase + (((uint32_t)(half*64 + 0))  ^ sw)) = v0;
            *(uint4*)(rbase + (((uint32_t)(half*64 + 16)) ^ sw)) = v1;
            *(uint4*)(rbase + (((uint32_t)(half*64 + 32)) ^ sw)) = v2;
            *(uint4*)(rbase + (((uint32_t)(half*64 + 48)) ^ sw)) = v3;
        }
        {
            const int krow = tid >> 2, q4 = tid & 3;
            const uint4* src = (const uint4*)(g_w_bf + (size_t)(k0 + krow) * HF + bn + q4 * 16);
            uint4 v0 = src[0], v1 = src[1];
            const uint32_t sw = (uint32_t)((krow & 7) << 4);
            char* rbase = smB + krow * 128;
            *(uint4*)(rbase + (((uint32_t)(q4*32 + 0))  ^ sw)) = v0;
            *(uint4*)(rbase + (((uint32_t)(q4*32 + 16)) ^ sw)) = v1;
        }
        __syncthreads();

#pragma unroll
        for (int kk = 0; kk < 4; kk++) {
            uint32_t ah[2][4];
#pragma unroll
            for (int mi = 0; mi < 2; mi++) {
                const int arow = mbase + mi * 16 + arow0;
                uint32_t addr = sa + (uint32_t)arow * 128u +
                    (((uint32_t)(kk * 32 + akh * 16)) ^ ((uint32_t)(arow & 7) << 4));
                LDSM4(ah[mi], addr);
            }
            uint32_t rowb = sbm + (uint32_t)(kk * 16 + joff) * 128u;
#pragma unroll
            for (int li = 0; li < 2; li++) {
                uint32_t b4[4];
                uint32_t off = ((uint32_t)((nbase + fmb + li * 16) * 2)) ^ swb;
                LDSM4T(b4, rowb + off);
                MMA(c[0][li*2],     ah[0], b4[0], b4[1]);
                MMA(c[1][li*2],     ah[1], b4[0], b4[1]);
                MMA(c[0][li*2 + 1], ah[0], b4[2], b4[3]);
                MMA(c[1][li*2 + 1], ah[1], b4[2], b4[3]);
            }
        }
    }
#pragma unroll
    for (int mi = 0; mi < 2; mi++)
#pragma unroll
        for (int u = 0; u < 2; u++) {
            const int row = bm + mbase + mi * 16 + u * 8 + g;
#pragma unroll
            for (int ng = 0; ng < 4; ng++) {
                const int col = bn + nbase + ng * 8 + 2 * t;
                float2 val;
                val.x = c[mi][ng][u*2 + 0];
                val.y = c[mi][ng][u*2 + 1];
                *(float2*)(g_mapped + (size_t)row * HF + col) = val;
            }
        }
}

// ---------------- el/er: 2 threads per (row,head), shfl combine ----------------
__global__ __launch_bounds__(256) void elr_kernel(const float* __restrict__ a) {
    int gid = blockIdx.x * 256 + threadIdx.x;       // over 2*B*N*H
    if (gid >= 2 * BB * NN * HH) return;
    int idx = gid >> 1, half = gid & 1;
    const float4* mp = (const float4*)&g_mapped[(size_t)idx * FF + half * 32];
    const float4* al = (const float4*)(a + half * 32);
    const float4* ar = (const float4*)(a + FF + half * 32);
    float el = 0.f, er = 0.f;
#pragma unroll
    for (int q = 0; q < 8; q++) {
        float4 v = mp[q], x = al[q], y = ar[q];
        el += v.x * x.x + v.y * x.y + v.z * x.z + v.w * x.w;
        er += v.x * y.x + v.y * y.y + v.z * y.z + v.w * y.w;
    }
    el += __shfl_xor_sync(0xffffffffu, el, 1);
    er += __shfl_xor_sync(0xffffffffu, er, 1);
    if (half == 0) {
        g_el[idx] = el * LOG2E;
        g_er[idx] = er * LOG2E;
    }
}

// ---------------- pack edges int32 -> byte -------------------------------------
__global__ __launch_bounds__(256) void pack_edges_kernel(const int* __restrict__ e) {
    size_t base = ((size_t)blockIdx.x * 256 + threadIdx.x) * 16;
    uint32_t out[4];
#pragma unroll
    for (int w = 0; w < 4; w++) {
        int4 v = *(const int4*)(e + base + w * 4);
        out[w] = (v.x ? 1u : 0u) | ((v.y ? 1u : 0u) << 8) |
                 ((v.z ? 1u : 0u) << 16) | ((v.w ? 1u : 0u) << 24);
    }
    uint4 o; o.x = out[0]; o.y = out[1]; o.z = out[2]; o.w = out[3];
    *(uint4*)(g_eb + base) = o;
}

// ---------------- attention: j-split x2, partial sums --------------------------
// grid (32, 2, 8): blockIdx.x = i-tile*2 + split. Each CTA does 8 j-tiles.
// Inner loop identical to passing R12/R13. Epilogue writes UNNORMALIZED
// partial acc + partial row-sums l (softmax partials are linear).
#define SV   0
#define SEB  16384
#define SER  34816
#define SM_AT 35328

#define PPAIR(DH, EL, ER2, EU, LACC) do{                                      \
    float e0 = (EL) + (ER2).x, e1 = (EL) + (ER2).y;                           \
    float s0 = fmaxf(e0, 0.2f * e0), s1 = fmaxf(e1, 0.2f * e1);               \
    float p0, p1;                                                             \
    asm("ex2.approx.f32 %0, %1;" : "=f"(p0) : "f"(s0));                       \
    asm("ex2.approx.f32 %0, %1;" : "=f"(p1) : "f"(s1));                       \
    p0 = ((EU) & 0xFFu)   ? p0 : 0.f;                                         \
    p1 = ((EU) & 0xFF00u) ? p1 : 0.f;                                         \
    (LACC) += p0 + p1;                                                        \
    asm("cvt.rn.bf16x2.f32 %0, %1, %2;" : "=r"(DH) : "f"(p1), "f"(p0));       \
} while(0)

__global__ __launch_bounds__(256) void attn_hmma_kernel(void) {
    extern __shared__ char smem[];
    const uint32_t sb = smem_u32(smem);
    const int tid = threadIdx.x, w = tid >> 5, lane = tid & 31;
    const int b = blockIdx.y, head = blockIdx.z;
    const int split = blockIdx.x & 1;
    const int i0 = (blockIdx.x >> 1) * 128;
    const int ib = w * 16;
    const int g = lane >> 2, t = lane & 3;

    float el_r[2];
    el_r[0] = g_el[((size_t)b*NN + i0 + ib + g)*HH + head];
    el_r[1] = g_el[((size_t)b*NN + i0 + ib + 8 + g)*HH + head];

    float c[8][4];
    float l_acc[2] = {0.f, 0.f};
#pragma unroll
    for (int ng = 0; ng < 8; ng++)
#pragma unroll
        for (int r = 0; r < 4; r++) c[ng][r] = 0.f;

    const int joff = ((lane >> 3) & 1) * 8 + (lane & 7);
    const int fmb  = (lane >> 4) * 8;
    const uint32_t sw = (uint32_t)((lane & 7) << 4);

    for (int tt = split * (TILES/NSPL); tt < (split + 1) * (TILES/NSPL); tt++) {
        const int j0 = tt * 128;
        __syncthreads();
        {   // stage V: 128j x 64f, f32 -> bf16, swizzled 128B rows
            const int j = tid >> 1, fh = (tid & 1) * 32;
            const float* src = g_mapped + ((size_t)b*NN + j0 + j)*HF + head*FF + fh;
            const uint32_t swj = (uint32_t)((j & 7) << 4);
#pragma unroll
            for (int q4 = 0; q4 < 8; q4++) {
                float4 v = *(const float4*)(src + q4*4);
                uint32_t h01, h23;
                asm("cvt.rn.bf16x2.f32 %0, %1, %2;" : "=r"(h01) : "f"(v.y), "f"(v.x));
                asm("cvt.rn.bf16x2.f32 %0, %1, %2;" : "=r"(h23) : "f"(v.w), "f"(v.z));
                uint32_t off = ((uint32_t)((fh + q4*4)*2)) ^ swj;
                asm volatile("st.shared.v2.b32 [%0], {%1,%2};"
                             :: "r"(sb + SV + (uint32_t)(j*128) + off), "r"(h01), "r"(h23) : "memory");
            }
        }
        {   // stage edges: 128 rows x 128B (row stride 144)
            const int row = tid >> 1, half = tid & 1;
            const uint4* esrc = (const uint4*)(g_eb + ((size_t)b*NN + i0 + row)*NN + j0 + half*64);
            char* edst = smem + SEB + row*144 + half*64;
            uint4 e0 = esrc[0], e1 = esrc[1], e2 = esrc[2], e3 = esrc[3];
            *(uint4*)(edst)      = e0;  *(uint4*)(edst + 16) = e1;
            *(uint4*)(edst + 32) = e2;  *(uint4*)(edst + 48) = e3;
        }
        if (tid < 128)
            ((float*)(smem + SER))[tid] = g_er[((size_t)b*NN + j0 + tid)*HH + head];
        __syncthreads();

#pragma unroll
        for (int tk = 0; tk < 8; tk++) {
            const int j0k = tk * 16;
            float2 erA = *(const float2*)(smem + SER + (j0k + 2*t)*4);
            float2 erB = *(const float2*)(smem + SER + (j0k + 8 + 2*t)*4);
            uint32_t ah[4];
            {
                uint32_t ea = sb + SEB + (uint32_t)((ib + g)*144 + j0k + 2*t);
                uint32_t eA0, eA1, eB0, eB1;
                asm volatile("ld.shared.u16 %0, [%1];"     : "=r"(eA0) : "r"(ea));
                asm volatile("ld.shared.u16 %0, [%1+8];"   : "=r"(eA1) : "r"(ea));
                asm volatile("ld.shared.u16 %0, [%1+1152];": "=r"(eB0) : "r"(ea));
                asm volatile("ld.shared.u16 %0, [%1+1160];": "=r"(eB1) : "r"(ea));
                PPAIR(ah[0], el_r[0], erA, eA0, l_acc[0]);
                PPAIR(ah[1], el_r[1], erA, eB0, l_acc[1]);
                PPAIR(ah[2], el_r[0], erB, eA1, l_acc[0]);
                PPAIR(ah[3], el_r[1], erB, eB1, l_acc[1]);
            }
            uint32_t rowb = sb + SV + (uint32_t)(j0k + joff)*128u;
#pragma unroll
            for (int li = 0; li < 4; li++) {
                uint32_t b4[4];
                uint32_t off = ((uint32_t)((fmb + li*16)*2)) ^ sw;
                LDSM4T(b4, rowb + off);
                MMA(c[li*2],     ah, b4[0], b4[1]);
                MMA(c[li*2 + 1], ah, b4[2], b4[3]);
            }
        }
    }

    // ---- epilogue: partial (unnormalized) acc + l ----
    float lsum[2];
#pragma unroll
    for (int k = 0; k < 2; k++) {
        float l = l_acc[k];
        l += __shfl_xor_sync(0xffffffffu, l, 1);
        l += __shfl_xor_sync(0xffffffffu, l, 2);
        lsum[k] = l;
    }
    float* pa = g_pacc + (size_t)split * ((size_t)BB*NN*HH*FF);
    float* pl = g_pl + split * (BB*NN*HH);
#pragma unroll
    for (int u = 0; u < 2; u++) {
        const int row = i0 + ib + u*8 + g;
        float* dst = pa + (((size_t)b*NN + row)*HH + head)*FF + 2*t;
#pragma unroll
        for (int ng = 0; ng < 8; ng++) {
            float2 val;
            val.x = c[ng][u*2 + 0];
            val.y = c[ng][u*2 + 1];
            *(float2*)(dst + ng*8) = val;
        }
        if (t == 0)
            pl[((size_t)b*NN + row)*HH + head] = lsum[u];
    }
}

// ---------------- combine: sum splits, normalize, mean, sigmoid ----------------
__global__ __launch_bounds__(256) void combine_kernel(float* __restrict__ out) {
    int idx = blockIdx.x * 256 + threadIdx.x;
    if (idx >= BB * NN * FF) return;
    int f = idx & 63;
    int bi = idx >> 6;
    const float* a0 = g_pacc;
    const float* a1 = g_pacc + (size_t)BB*NN*HH*FF;
    const float* l0 = g_pl;
    const float* l1 = g_pl + BB*NN*HH;
    float s = 0.f;
#pragma unroll
    for (int h = 0; h < HH; h++) {
        float l = l0[(size_t)bi*HH + h] + l1[(size_t)bi*HH + h];
        float v = a0[((size_t)bi*HH + h)*FF + f] + a1[((size_t)bi*HH + h)*FF + f];
        s += v * (1.f / l);
    }
    s *= 0.125f;
    out[idx] = 1.f / (1.f + __expf(-s));
}

// ---------------- launch -------------------------------------------------------
extern "C" void kernel_launch(void* const* d_in, const int* in_sizes, int n_in,
                              void* d_out, int out_size) {
    const float* nodes = (const float*)d_in[0];
    const int*   edges = (const int*)d_in[1];
    const float* W     = (const float*)d_in[2];
    const float* a     = (const float*)d_in[3];
    float* out = (float*)d_out;

    cvt_nodes_kernel<<<(BB*NN*DIN/4)/256, 256>>>((const float4*)nodes);
    cvt_w_kernel<<<(DIN*HF/4)/256, 256>>>((const float4*)W);

    dim3 ggrid(HF / 64, (BB * NN) / 128);    // (8, 32) = 256 CTAs
    gemm_hmma_kernel<<<ggrid, 256>>>();

    elr_kernel<<<(2 * BB * NN * HH + 255) / 256, 256>>>(a);

    pack_edges_kernel<<<(BB * NN * NN) / (256 * 16), 256>>>(edges);

    dim3 agrid(NSPL * NN / 128, BB, HH);     // (32, 2, 8) = 512 CTAs
    attn_hmma_kernel<<<agrid, 256, SM_AT>>>();

    combine_kernel<<<(BB * NN * FF + 255) / 256, 256>>>(out);
}